// round 2
// baseline (speedup 1.0000x reference)
#include <cuda_runtime.h>

// Problem constants (validated against in_sizes at launch)
#define NN 50000
#define EE 800000

// ---------------- device scratch (no allocations allowed) ----------------
__device__ int   d_deg[NN];
__device__ int   d_cursor[NN];
__device__ int   d_rowstart[NN + 1];
__device__ int   d_edgeidx[EE];
__device__ float d_hneigh[(size_t)NN * 256];   // mean(concat[src_h, edge_h]) per node
__device__ float d_h1[(size_t)NN * 128];       // layer-1 node output
__device__ float d_e1[(size_t)EE * 128];       // layer-1 edge output

// ---------------- CSR build ----------------
__global__ void zero_counts_kernel(int n) {
    int i = blockIdx.x * blockDim.x + threadIdx.x;
    if (i < n) { d_deg[i] = 0; d_cursor[i] = 0; }
}

__global__ void hist_kernel(const int* __restrict__ v, int E) {
    int i = blockIdx.x * blockDim.x + threadIdx.x;
    if (i < E) atomicAdd(&d_deg[v[i]], 1);
}

// Single-block scan: each thread serially sums a contiguous slice, one
// Hillis-Steele block scan over the 1024 partials, then writes prefixes.
__global__ void scan_kernel(int n) {
    __shared__ int sh[1024];
    int tid = threadIdx.x;
    int per = (n + 1023) / 1024;
    int s = tid * per;
    int e = min(s + per, n);
    int sum = 0;
    for (int i = s; i < e; ++i) sum += d_deg[i];
    sh[tid] = sum;
    __syncthreads();
    #pragma unroll
    for (int off = 1; off < 1024; off <<= 1) {
        int t = (tid >= off) ? sh[tid - off] : 0;
        __syncthreads();
        sh[tid] += t;
        __syncthreads();
    }
    int run = (tid == 0) ? 0 : sh[tid - 1];
    if (tid == 0) d_rowstart[0] = 0;
    for (int i = s; i < e; ++i) {
        run += d_deg[i];
        d_rowstart[i + 1] = run;
    }
}

__global__ void bucket_kernel(const int* __restrict__ v, int E) {
    int i = blockIdx.x * blockDim.x + threadIdx.x;
    if (i < E) {
        int d = v[i];
        int p = atomicAdd(&d_cursor[d], 1);
        d_edgeidx[d_rowstart[d] + p] = i;
    }
}

// ---------------- aggregation: warp per node, atomic-free ----------------
// Lane l accumulates channels [8l, 8l+8) of the 256-wide message
// concat(srcf[u[e]], edgef[e]); divides by max(deg,1); writes d_hneigh.
// 2-wide unrolled for MLP on the random row gathers.
__global__ void agg_kernel(const float* __restrict__ srcf,
                           const float* __restrict__ edgef,
                           const int* __restrict__ u, int n) {
    int w = (blockIdx.x * blockDim.x + threadIdx.x) >> 5;
    int lane = threadIdx.x & 31;
    if (w >= n) return;
    int rs = d_rowstart[w];
    int re = d_rowstart[w + 1];
    int c = lane * 8;
    bool isA = (c < 128);
    int off = isA ? c : (c - 128);

    float4 a0 = make_float4(0.f, 0.f, 0.f, 0.f);
    float4 a1 = make_float4(0.f, 0.f, 0.f, 0.f);
    float4 b0 = make_float4(0.f, 0.f, 0.f, 0.f);
    float4 b1 = make_float4(0.f, 0.f, 0.f, 0.f);

    int p = rs;
    for (; p + 1 < re; p += 2) {
        int e0 = d_edgeidx[p];
        int e1 = d_edgeidx[p + 1];
        const float* s0 = isA ? (srcf + (size_t)u[e0] * 128 + off)
                              : (edgef + (size_t)e0 * 128 + off);
        const float* s1 = isA ? (srcf + (size_t)u[e1] * 128 + off)
                              : (edgef + (size_t)e1 * 128 + off);
        float4 x0 = *(const float4*)(s0);
        float4 x1 = *(const float4*)(s0 + 4);
        float4 y0 = *(const float4*)(s1);
        float4 y1 = *(const float4*)(s1 + 4);
        a0.x += x0.x; a0.y += x0.y; a0.z += x0.z; a0.w += x0.w;
        a1.x += x1.x; a1.y += x1.y; a1.z += x1.z; a1.w += x1.w;
        b0.x += y0.x; b0.y += y0.y; b0.z += y0.z; b0.w += y0.w;
        b1.x += y1.x; b1.y += y1.y; b1.z += y1.z; b1.w += y1.w;
    }
    if (p < re) {
        int e0 = d_edgeidx[p];
        const float* s0 = isA ? (srcf + (size_t)u[e0] * 128 + off)
                              : (edgef + (size_t)e0 * 128 + off);
        float4 x0 = *(const float4*)(s0);
        float4 x1 = *(const float4*)(s0 + 4);
        a0.x += x0.x; a0.y += x0.y; a0.z += x0.z; a0.w += x0.w;
        a1.x += x1.x; a1.y += x1.y; a1.z += x1.z; a1.w += x1.w;
    }
    a0.x += b0.x; a0.y += b0.y; a0.z += b0.z; a0.w += b0.w;
    a1.x += b1.x; a1.y += b1.y; a1.z += b1.z; a1.w += b1.w;

    float inv = 1.0f / fmaxf((float)(re - rs), 1.0f);
    a0.x *= inv; a0.y *= inv; a0.z *= inv; a0.w *= inv;
    a1.x *= inv; a1.y *= inv; a1.z *= inv; a1.w *= inv;
    float* o = d_hneigh + (size_t)w * 256 + c;
    *(float4*)(o)     = a0;
    *(float4*)(o + 4) = a1;
}

// ---------------- generic tiled GEMM with 2-segment concat X ----------------
// C[M,128] = relu( X[M,K] @ W[128,K]^T + bias ),  K = widthA + widthB
// X[r, k] = k < widthA ? segA[rowIdxA(r)*widthA + k]
//                      : segB[rowIdxB(r)*widthB + k - widthA]
// rowIdx*(r) = idx ? idx[r] : r   (gather for edge GEMMs)
// Double-buffered smem, register-staged prefetch, 1 sync per K-step.
#define BM 128
#define BN 128
#define BK 16

__global__ __launch_bounds__(256, 2)
void gemm_concat_relu(const float* __restrict__ segA, const int* __restrict__ idxA, int widthA,
                      const float* __restrict__ segB, const int* __restrict__ idxB, int widthB,
                      const float* __restrict__ W, const float* __restrict__ bias,
                      float* __restrict__ C, int M, int K) {
    __shared__ float Xs[2][BK][BM + 4];
    __shared__ float Ws[2][BK][BN + 4];

    const int t  = threadIdx.x;
    const int r0 = blockIdx.x * BM;
    const int kv = t & 3;        // float4 slot along k (0..3)
    const int rX = t >> 2;       // 0..63: load row / W col group
    const int tx = t & 15;       // output col group (8 cols)
    const int ty = t >> 4;       // output row group (8 rows)

    // resolve per-thread gather rows once
    const float* rowA[2];
    const float* rowB[2];
    bool valid[2];
    #pragma unroll
    for (int j = 0; j < 2; ++j) {
        int grow = r0 + rX + 64 * j;
        valid[j] = (grow < M);
        int g  = valid[j] ? grow : 0;
        int ia = idxA ? idxA[g] : g;
        int ib = idxB ? idxB[g] : g;
        rowA[j] = segA + (size_t)ia * widthA;
        rowB[j] = segB + (size_t)ib * widthB;
    }

    float acc[8][8];
    #pragma unroll
    for (int i = 0; i < 8; ++i)
        #pragma unroll
        for (int j = 0; j < 8; ++j) acc[i][j] = 0.f;

    const int NT = K / BK;
    float4 px[2], pw[2];

    // ---- prologue: fetch tile 0 into regs, stash in buffer 0 ----
    {
        int k = 0 + kv * 4;
        #pragma unroll
        for (int j = 0; j < 2; ++j) {
            px[j] = make_float4(0.f, 0.f, 0.f, 0.f);
            if (valid[j])
                px[j] = (k < widthA) ? *(const float4*)(rowA[j] + k)
                                     : *(const float4*)(rowB[j] + (k - widthA));
            pw[j] = *(const float4*)(W + (size_t)(rX + 64 * j) * K + k);
        }
        #pragma unroll
        for (int j = 0; j < 2; ++j) {
            int r = rX + 64 * j;
            Xs[0][kv * 4 + 0][r] = px[j].x;
            Xs[0][kv * 4 + 1][r] = px[j].y;
            Xs[0][kv * 4 + 2][r] = px[j].z;
            Xs[0][kv * 4 + 3][r] = px[j].w;
            Ws[0][kv * 4 + 0][r] = pw[j].x;
            Ws[0][kv * 4 + 1][r] = pw[j].y;
            Ws[0][kv * 4 + 2][r] = pw[j].z;
            Ws[0][kv * 4 + 3][r] = pw[j].w;
        }
    }
    __syncthreads();

    for (int tstep = 0; tstep < NT; ++tstep) {
        // prefetch next tile into registers (overlaps with compute below)
        if (tstep + 1 < NT) {
            int k = (tstep + 1) * BK + kv * 4;
            #pragma unroll
            for (int j = 0; j < 2; ++j) {
                px[j] = make_float4(0.f, 0.f, 0.f, 0.f);
                if (valid[j])
                    px[j] = (k < widthA) ? *(const float4*)(rowA[j] + k)
                                         : *(const float4*)(rowB[j] + (k - widthA));
                pw[j] = *(const float4*)(W + (size_t)(rX + 64 * j) * K + k);
            }
        }

        const int buf = tstep & 1;
        #pragma unroll
        for (int kk = 0; kk < BK; ++kk) {
            float4 a0 = *(const float4*)&Xs[buf][kk][ty * 8];
            float4 a1 = *(const float4*)&Xs[buf][kk][ty * 8 + 4];
            float4 c0 = *(const float4*)&Ws[buf][kk][tx * 8];
            float4 c1 = *(const float4*)&Ws[buf][kk][tx * 8 + 4];
            float a[8] = {a0.x, a0.y, a0.z, a0.w, a1.x, a1.y, a1.z, a1.w};
            float b[8] = {c0.x, c0.y, c0.z, c0.w, c1.x, c1.y, c1.z, c1.w};
            #pragma unroll
            for (int i = 0; i < 8; ++i)
                #pragma unroll
                for (int j = 0; j < 8; ++j)
                    acc[i][j] = fmaf(a[i], b[j], acc[i][j]);
        }

        if (tstep + 1 < NT) {
            const int nb = (tstep + 1) & 1;
            #pragma unroll
            for (int j = 0; j < 2; ++j) {
                int r = rX + 64 * j;
                Xs[nb][kv * 4 + 0][r] = px[j].x;
                Xs[nb][kv * 4 + 1][r] = px[j].y;
                Xs[nb][kv * 4 + 2][r] = px[j].z;
                Xs[nb][kv * 4 + 3][r] = px[j].w;
                Ws[nb][kv * 4 + 0][r] = pw[j].x;
                Ws[nb][kv * 4 + 1][r] = pw[j].y;
                Ws[nb][kv * 4 + 2][r] = pw[j].z;
                Ws[nb][kv * 4 + 3][r] = pw[j].w;
            }
            __syncthreads();
        }
    }

    // epilogue: bias + relu, float4 stores
    float4 bb0 = *(const float4*)(bias + tx * 8);
    float4 bb1 = *(const float4*)(bias + tx * 8 + 4);
    float bv[8] = {bb0.x, bb0.y, bb0.z, bb0.w, bb1.x, bb1.y, bb1.z, bb1.w};
    #pragma unroll
    for (int i = 0; i < 8; ++i) {
        int grow = r0 + ty * 8 + i;
        if (grow < M) {
            float o[8];
            #pragma unroll
            for (int j = 0; j < 8; ++j)
                o[j] = fmaxf(acc[i][j] + bv[j], 0.f);
            float* cp = C + (size_t)grow * 128 + tx * 8;
            *(float4*)(cp)     = make_float4(o[0], o[1], o[2], o[3]);
            *(float4*)(cp + 4) = make_float4(o[4], o[5], o[6], o[7]);
        }
    }
}

// ---------------- launch ----------------
extern "C" void kernel_launch(void* const* d_in, const int* in_sizes, int n_in,
                              void* d_out, int out_size) {
    const float* nf  = (const float*)d_in[0];
    const float* ef  = (const float*)d_in[1];
    const int*   u   = (const int*)d_in[2];
    const int*   v   = (const int*)d_in[3];
    const float* W1a = (const float*)d_in[4];
    const float* b1a = (const float*)d_in[5];
    const float* W1e = (const float*)d_in[6];
    const float* b1e = (const float*)d_in[7];
    const float* W2a = (const float*)d_in[8];
    const float* b2a = (const float*)d_in[9];
    const float* W2e = (const float*)d_in[10];
    const float* b2e = (const float*)d_in[11];
    float* out = (float*)d_out;

    int N = in_sizes[0] / 128;
    int E = in_sizes[2];
    if (N > NN) N = NN;
    if (E > EE) E = EE;

    float *hneigh, *h1, *e1;
    cudaGetSymbolAddress((void**)&hneigh, d_hneigh);
    cudaGetSymbolAddress((void**)&h1, d_h1);
    cudaGetSymbolAddress((void**)&e1, d_e1);

    // CSR by destination (rebuilt every launch)
    zero_counts_kernel<<<(N + 255) / 256, 256>>>(N);
    hist_kernel<<<(E + 255) / 256, 256>>>(v, E);
    scan_kernel<<<1, 1024>>>(N);
    bucket_kernel<<<(E + 255) / 256, 256>>>(v, E);

    // ---- layer 1 ----
    agg_kernel<<<(N + 7) / 8, 256>>>(nf, ef, u, N);
    gemm_concat_relu<<<(N + BM - 1) / BM, 256>>>(nf, nullptr, 128,
                                                 hneigh, nullptr, 256,
                                                 W1a, b1a, h1, N, 384);
    gemm_concat_relu<<<(E + BM - 1) / BM, 256>>>(h1, u, 128,
                                                 h1, v, 128,
                                                 W1e, b1e, e1, E, 256);

    // ---- layer 2 ----
    agg_kernel<<<(N + 7) / 8, 256>>>(h1, e1, u, N);
    gemm_concat_relu<<<(N + BM - 1) / BM, 256>>>(h1, nullptr, 128,
                                                 hneigh, nullptr, 256,
                                                 W2a, b2a, out, N, 384);
    gemm_concat_relu<<<(E + BM - 1) / BM, 256>>>(out, u, 128,
                                                 out, v, 128,
                                                 W2e, b2e, out + (size_t)N * 128, E, 256);
}

// round 5
// speedup vs baseline: 1.8913x; 1.8913x over previous
#include <cuda_runtime.h>
#include <cstdint>

// Problem constants
#define NN 50000
#define EE 800000

// ---------------- device scratch ----------------
__device__ int   d_deg[NN];
__device__ int   d_cursor[NN];
__device__ int   d_rowstart[NN + 1];
__device__ int   d_edgeidx[EE];
__device__ float d_hneigh[(size_t)NN * 256];
__device__ float d_h1[(size_t)NN * 128];
__device__ float d_e1[(size_t)EE * 128];

// ---------------- CSR build ----------------
__global__ void zero_counts_kernel(int n) {
    int i = blockIdx.x * blockDim.x + threadIdx.x;
    if (i < n) { d_deg[i] = 0; d_cursor[i] = 0; }
}
__global__ void hist_kernel(const int* __restrict__ v, int E) {
    int i = blockIdx.x * blockDim.x + threadIdx.x;
    if (i < E) atomicAdd(&d_deg[v[i]], 1);
}
__global__ void scan_kernel(int n) {
    __shared__ int sh[1024];
    int tid = threadIdx.x;
    int per = (n + 1023) / 1024;
    int s = tid * per, e = min(s + per, n);
    int sum = 0;
    for (int i = s; i < e; ++i) sum += d_deg[i];
    sh[tid] = sum;
    __syncthreads();
    #pragma unroll
    for (int off = 1; off < 1024; off <<= 1) {
        int t = (tid >= off) ? sh[tid - off] : 0;
        __syncthreads();
        sh[tid] += t;
        __syncthreads();
    }
    int run = (tid == 0) ? 0 : sh[tid - 1];
    if (tid == 0) d_rowstart[0] = 0;
    for (int i = s; i < e; ++i) { run += d_deg[i]; d_rowstart[i + 1] = run; }
}
__global__ void bucket_kernel(const int* __restrict__ v, int E) {
    int i = blockIdx.x * blockDim.x + threadIdx.x;
    if (i < E) {
        int d = v[i];
        int p = atomicAdd(&d_cursor[d], 1);
        d_edgeidx[d_rowstart[d] + p] = i;
    }
}

// ---------------- aggregation: warp per node, atomic-free ----------------
__global__ void agg_kernel(const float* __restrict__ srcf,
                           const float* __restrict__ edgef,
                           const int* __restrict__ u, int n) {
    int w = (blockIdx.x * blockDim.x + threadIdx.x) >> 5;
    int lane = threadIdx.x & 31;
    if (w >= n) return;
    int rs = d_rowstart[w];
    int re = d_rowstart[w + 1];
    int c = lane * 8;
    bool isA = (c < 128);
    int off = isA ? c : (c - 128);

    float4 a0 = make_float4(0.f, 0.f, 0.f, 0.f);
    float4 a1 = make_float4(0.f, 0.f, 0.f, 0.f);
    float4 b0 = make_float4(0.f, 0.f, 0.f, 0.f);
    float4 b1 = make_float4(0.f, 0.f, 0.f, 0.f);

    int p = rs;
    for (; p + 1 < re; p += 2) {
        int e0 = d_edgeidx[p];
        int e1 = d_edgeidx[p + 1];
        const float* s0 = isA ? (srcf + (size_t)u[e0] * 128 + off)
                              : (edgef + (size_t)e0 * 128 + off);
        const float* s1 = isA ? (srcf + (size_t)u[e1] * 128 + off)
                              : (edgef + (size_t)e1 * 128 + off);
        float4 x0 = *(const float4*)(s0);
        float4 x1 = *(const float4*)(s0 + 4);
        float4 y0 = *(const float4*)(s1);
        float4 y1 = *(const float4*)(s1 + 4);
        a0.x += x0.x; a0.y += x0.y; a0.z += x0.z; a0.w += x0.w;
        a1.x += x1.x; a1.y += x1.y; a1.z += x1.z; a1.w += x1.w;
        b0.x += y0.x; b0.y += y0.y; b0.z += y0.z; b0.w += y0.w;
        b1.x += y1.x; b1.y += y1.y; b1.z += y1.z; b1.w += y1.w;
    }
    if (p < re) {
        int e0 = d_edgeidx[p];
        const float* s0 = isA ? (srcf + (size_t)u[e0] * 128 + off)
                              : (edgef + (size_t)e0 * 128 + off);
        float4 x0 = *(const float4*)(s0);
        float4 x1 = *(const float4*)(s0 + 4);
        a0.x += x0.x; a0.y += x0.y; a0.z += x0.z; a0.w += x0.w;
        a1.x += x1.x; a1.y += x1.y; a1.z += x1.z; a1.w += x1.w;
    }
    a0.x += b0.x; a0.y += b0.y; a0.z += b0.z; a0.w += b0.w;
    a1.x += b1.x; a1.y += b1.y; a1.z += b1.z; a1.w += b1.w;

    float inv = 1.0f / fmaxf((float)(re - rs), 1.0f);
    a0.x *= inv; a0.y *= inv; a0.z *= inv; a0.w *= inv;
    a1.x *= inv; a1.y *= inv; a1.z *= inv; a1.w *= inv;
    float* o = d_hneigh + (size_t)w * 256 + c;
    *(float4*)(o)     = a0;
    *(float4*)(o + 4) = a1;
}

// ---------------- tf32 mma.sync GEMM ----------------
// C[M,128] = relu( X[M,K] @ W[128,K]^T + bias ), K in {256, 384}
// X row r = concat(segA[idxA(r)][0:widthA], segB[idxB(r)][0:widthB])
// Block: 128x128, 8 warps (2M x 4N), warp tile 64x32 = 4x4 m16n8k8 frags.
// K chunked by 16; double-buffered smem + register prefetch.

__device__ __forceinline__ uint32_t f2tf32(float x) {
    uint32_t r;
    asm("cvt.rna.tf32.f32 %0, %1;" : "=r"(r) : "f"(x));
    return r;
}
__device__ __forceinline__ void mma1688(float* c, const uint32_t* a, const uint32_t* b) {
    asm volatile(
        "mma.sync.aligned.m16n8k8.row.col.f32.tf32.tf32.f32 "
        "{%0,%1,%2,%3}, {%4,%5,%6,%7}, {%8,%9}, {%0,%1,%2,%3};"
        : "+f"(c[0]), "+f"(c[1]), "+f"(c[2]), "+f"(c[3])
        : "r"(a[0]), "r"(a[1]), "r"(a[2]), "r"(a[3]), "r"(b[0]), "r"(b[1]));
}

#define RS 20   // smem row stride in words (conflict-free for fragment loads)

__global__ __launch_bounds__(256, 2)
void gemm_tc(const float* __restrict__ segA, const int* __restrict__ idxA, int widthA,
             const float* __restrict__ segB, const int* __restrict__ idxB, int widthB,
             const float* __restrict__ W, const float* __restrict__ bias,
             float* __restrict__ C, int M, int K) {
    __shared__ uint32_t Xs[2][128 * RS];
    __shared__ uint32_t Ws[2][128 * RS];

    const int tid  = threadIdx.x;
    const int wid  = tid >> 5;
    const int lane = tid & 31;
    const int blk  = blockIdx.x;
    const int wm   = wid & 1;    // 0..1: M warp coord (64 rows)
    const int wn   = wid >> 1;   // 0..3: N warp coord (32 cols)
    const int g    = lane >> 2;  // group id
    const int t    = lane & 3;   // thread-in-group

    // ---- load assignment: row = tid>>1 (0..127), k-half = (tid&1)*8 ----
    const int rloc = tid >> 1;
    const int kh   = (tid & 1) * 8;
    int grow = blk * 128 + rloc;
    int grd  = (grow < M) ? grow : 0;
    const float* pA = segA + (size_t)(idxA ? idxA[grd] : grd) * widthA;
    const float* pB = segB + (size_t)(idxB ? idxB[grd] : grd) * widthB;
    const float* pW = W + (size_t)rloc * K;

    float cacc[4][4][4];
    #pragma unroll
    for (int mi = 0; mi < 4; ++mi)
        #pragma unroll
        for (int ni = 0; ni < 4; ++ni)
            #pragma unroll
            for (int r = 0; r < 4; ++r) cacc[mi][ni][r] = 0.f;

    const int NC = K >> 4;   // chunks of 16
    float4 px0, px1, pw0, pw1;

    // prologue: chunk 0 -> regs -> smem buf0
    {
        int k = kh;
        px0 = (k < widthA) ? *(const float4*)(pA + k) : *(const float4*)(pB + (k - widthA));
        k += 4;
        px1 = (k < widthA) ? *(const float4*)(pA + k) : *(const float4*)(pB + (k - widthA));
        pw0 = *(const float4*)(pW + kh);
        pw1 = *(const float4*)(pW + kh + 4);
        uint32_t* dx = &Xs[0][rloc * RS + kh];
        uint32_t* dw = &Ws[0][rloc * RS + kh];
        dx[0] = f2tf32(px0.x); dx[1] = f2tf32(px0.y); dx[2] = f2tf32(px0.z); dx[3] = f2tf32(px0.w);
        dx[4] = f2tf32(px1.x); dx[5] = f2tf32(px1.y); dx[6] = f2tf32(px1.z); dx[7] = f2tf32(px1.w);
        dw[0] = f2tf32(pw0.x); dw[1] = f2tf32(pw0.y); dw[2] = f2tf32(pw0.z); dw[3] = f2tf32(pw0.w);
        dw[4] = f2tf32(pw1.x); dw[5] = f2tf32(pw1.y); dw[6] = f2tf32(pw1.z); dw[7] = f2tf32(pw1.w);
    }
    __syncthreads();

    for (int c = 0; c < NC; ++c) {
        // prefetch next chunk to registers (overlaps with MMA below)
        if (c + 1 < NC) {
            int kb = (c + 1) * 16 + kh;
            int k = kb;
            px0 = (k < widthA) ? *(const float4*)(pA + k) : *(const float4*)(pB + (k - widthA));
            k += 4;
            px1 = (k < widthA) ? *(const float4*)(pA + k) : *(const float4*)(pB + (k - widthA));
            pw0 = *(const float4*)(pW + kb);
            pw1 = *(const float4*)(pW + kb + 4);
        }

        const int buf = c & 1;
        #pragma unroll
        for (int ks = 0; ks < 2; ++ks) {
            const int ko = ks * 8;
            uint32_t af[4][4];
            #pragma unroll
            for (int mi = 0; mi < 4; ++mi) {
                int r0 = (wm * 64 + mi * 16 + g) * RS + ko + t;
                af[mi][0] = Xs[buf][r0];
                af[mi][1] = Xs[buf][r0 + 8 * RS];
                af[mi][2] = Xs[buf][r0 + 4];
                af[mi][3] = Xs[buf][r0 + 8 * RS + 4];
            }
            #pragma unroll
            for (int ni = 0; ni < 4; ++ni) {
                uint32_t bf[2];
                int n0 = (wn * 32 + ni * 8 + g) * RS + ko + t;
                bf[0] = Ws[buf][n0];
                bf[1] = Ws[buf][n0 + 4];
                #pragma unroll
                for (int mi = 0; mi < 4; ++mi)
                    mma1688(cacc[mi][ni], af[mi], bf);
            }
        }

        if (c + 1 < NC) {
            const int nb = (c + 1) & 1;
            uint32_t* dx = &Xs[nb][rloc * RS + kh];
            uint32_t* dw = &Ws[nb][rloc * RS + kh];
            dx[0] = f2tf32(px0.x); dx[1] = f2tf32(px0.y); dx[2] = f2tf32(px0.z); dx[3] = f2tf32(px0.w);
            dx[4] = f2tf32(px1.x); dx[5] = f2tf32(px1.y); dx[6] = f2tf32(px1.z); dx[7] = f2tf32(px1.w);
            dw[0] = f2tf32(pw0.x); dw[1] = f2tf32(pw0.y); dw[2] = f2tf32(pw0.z); dw[3] = f2tf32(pw0.w);
            dw[4] = f2tf32(pw1.x); dw[5] = f2tf32(pw1.y); dw[6] = f2tf32(pw1.z); dw[7] = f2tf32(pw1.w);
            __syncthreads();
        }
    }

    // epilogue: bias + relu, float2 stores
    #pragma unroll
    for (int ni = 0; ni < 4; ++ni) {
        int col = wn * 32 + ni * 8 + t * 2;
        float b0 = bias[col];
        float b1 = bias[col + 1];
        #pragma unroll
        for (int mi = 0; mi < 4; ++mi) {
            int rb = blk * 128 + wm * 64 + mi * 16 + g;
            if (rb < M) {
                float2 o;
                o.x = fmaxf(cacc[mi][ni][0] + b0, 0.f);
                o.y = fmaxf(cacc[mi][ni][1] + b1, 0.f);
                *(float2*)(C + (size_t)rb * 128 + col) = o;
            }
            if (rb + 8 < M) {
                float2 o;
                o.x = fmaxf(cacc[mi][ni][2] + b0, 0.f);
                o.y = fmaxf(cacc[mi][ni][3] + b1, 0.f);
                *(float2*)(C + (size_t)(rb + 8) * 128 + col) = o;
            }
        }
    }
}

// ---------------- launch ----------------
extern "C" void kernel_launch(void* const* d_in, const int* in_sizes, int n_in,
                              void* d_out, int out_size) {
    const float* nf  = (const float*)d_in[0];
    const float* ef  = (const float*)d_in[1];
    const int*   u   = (const int*)d_in[2];
    const int*   v   = (const int*)d_in[3];
    const float* W1a = (const float*)d_in[4];
    const float* b1a = (const float*)d_in[5];
    const float* W1e = (const float*)d_in[6];
    const float* b1e = (const float*)d_in[7];
    const float* W2a = (const float*)d_in[8];
    const float* b2a = (const float*)d_in[9];
    const float* W2e = (const float*)d_in[10];
    const float* b2e = (const float*)d_in[11];
    float* out = (float*)d_out;

    int N = in_sizes[0] / 128;
    int E = in_sizes[2];
    if (N > NN) N = NN;
    if (E > EE) E = EE;

    float *hneigh, *h1, *e1;
    cudaGetSymbolAddress((void**)&hneigh, d_hneigh);
    cudaGetSymbolAddress((void**)&h1, d_h1);
    cudaGetSymbolAddress((void**)&e1, d_e1);

    // CSR by destination
    zero_counts_kernel<<<(N + 255) / 256, 256>>>(N);
    hist_kernel<<<(E + 255) / 256, 256>>>(v, E);
    scan_kernel<<<1, 1024>>>(N);
    bucket_kernel<<<(E + 255) / 256, 256>>>(v, E);

    int nb_node = (N + 127) / 128;
    int nb_edge = (E + 127) / 128;

    // ---- layer 1 ----
    agg_kernel<<<(N + 7) / 8, 256>>>(nf, ef, u, N);
    gemm_tc<<<nb_node, 256>>>(nf, nullptr, 128,
                              hneigh, nullptr, 256,
                              W1a, b1a, h1, N, 384);
    gemm_tc<<<nb_edge, 256>>>(h1, u, 128,
                              h1, v, 128,
                              W1e, b1e, e1, E, 256);

    // ---- layer 2 ----
    agg_kernel<<<(N + 7) / 8, 256>>>(h1, e1, u, N);
    gemm_tc<<<nb_node, 256>>>(h1, nullptr, 128,
                              hneigh, nullptr, 256,
                              W2a, b2a, out, N, 384);
    gemm_tc<<<nb_edge, 256>>>(out, u, 128,
                              out, v, 128,
                              W2e, b2e, out + (size_t)N * 128, E, 256);
}

// round 11
// speedup vs baseline: 4.7232x; 2.4974x over previous
#include <cuda_runtime.h>
#include <cstdint>

// Problem constants
#define NN 50000
#define EE 800000

// ---------------- device scratch ----------------
__device__ int   d_deg[NN];
__device__ int   d_cursor[NN];
__device__ int   d_rowstart[NN + 1];
__device__ int   d_edgeidx[EE];
__device__ float d_hneigh[(size_t)NN * 256];
__device__ float d_h1[(size_t)NN * 128];
__device__ float d_P[(size_t)NN * 128];
__device__ float d_Q[(size_t)NN * 128];

// ---------------- CSR build ----------------
__global__ void zero_counts_kernel(int n) {
    int i = blockIdx.x * blockDim.x + threadIdx.x;
    if (i < n) { d_deg[i] = 0; d_cursor[i] = 0; }
}
__global__ void hist_kernel(const int* __restrict__ v, int E) {
    int i = blockIdx.x * blockDim.x + threadIdx.x;
    if (i < E) atomicAdd(&d_deg[v[i]], 1);
}
__global__ void scan_kernel(int n) {
    __shared__ int sh[1024];
    int tid = threadIdx.x;
    int per = (n + 1023) / 1024;
    int s = tid * per, e = min(s + per, n);
    int sum = 0;
    for (int i = s; i < e; ++i) sum += d_deg[i];
    sh[tid] = sum;
    __syncthreads();
    #pragma unroll
    for (int off = 1; off < 1024; off <<= 1) {
        int t = (tid >= off) ? sh[tid - off] : 0;
        __syncthreads();
        sh[tid] += t;
        __syncthreads();
    }
    int run = (tid == 0) ? 0 : sh[tid - 1];
    if (tid == 0) d_rowstart[0] = 0;
    for (int i = s; i < e; ++i) { run += d_deg[i]; d_rowstart[i + 1] = run; }
}
__global__ void bucket_kernel(const int* __restrict__ v, int E) {
    int i = blockIdx.x * blockDim.x + threadIdx.x;
    if (i < E) {
        int d = v[i];
        int p = atomicAdd(&d_cursor[d], 1);
        d_edgeidx[d_rowstart[d] + p] = i;
    }
}

// ---------------- layer-1 aggregation: warp per node ----------------
__global__ void agg_kernel(const float* __restrict__ srcf,
                           const float* __restrict__ edgef,
                           const int* __restrict__ u, int n) {
    int w = (blockIdx.x * blockDim.x + threadIdx.x) >> 5;
    int lane = threadIdx.x & 31;
    if (w >= n) return;
    int rs = d_rowstart[w];
    int re = d_rowstart[w + 1];
    int c = lane * 8;
    bool isA = (c < 128);
    int off = isA ? c : (c - 128);

    float4 a0 = make_float4(0.f, 0.f, 0.f, 0.f);
    float4 a1 = make_float4(0.f, 0.f, 0.f, 0.f);
    float4 b0 = make_float4(0.f, 0.f, 0.f, 0.f);
    float4 b1 = make_float4(0.f, 0.f, 0.f, 0.f);

    int p = rs;
    for (; p + 1 < re; p += 2) {
        int e0 = d_edgeidx[p];
        int e1 = d_edgeidx[p + 1];
        const float* s0 = isA ? (srcf + (size_t)u[e0] * 128 + off)
                              : (edgef + (size_t)e0 * 128 + off);
        const float* s1 = isA ? (srcf + (size_t)u[e1] * 128 + off)
                              : (edgef + (size_t)e1 * 128 + off);
        float4 x0 = *(const float4*)(s0);
        float4 x1 = *(const float4*)(s0 + 4);
        float4 y0 = *(const float4*)(s1);
        float4 y1 = *(const float4*)(s1 + 4);
        a0.x += x0.x; a0.y += x0.y; a0.z += x0.z; a0.w += x0.w;
        a1.x += x1.x; a1.y += x1.y; a1.z += x1.z; a1.w += x1.w;
        b0.x += y0.x; b0.y += y0.y; b0.z += y0.z; b0.w += y0.w;
        b1.x += y1.x; b1.y += y1.y; b1.z += y1.z; b1.w += y1.w;
    }
    if (p < re) {
        int e0 = d_edgeidx[p];
        const float* s0 = isA ? (srcf + (size_t)u[e0] * 128 + off)
                              : (edgef + (size_t)e0 * 128 + off);
        float4 x0 = *(const float4*)(s0);
        float4 x1 = *(const float4*)(s0 + 4);
        a0.x += x0.x; a0.y += x0.y; a0.z += x0.z; a0.w += x0.w;
        a1.x += x1.x; a1.y += x1.y; a1.z += x1.z; a1.w += x1.w;
    }
    a0.x += b0.x; a0.y += b0.y; a0.z += b0.z; a0.w += b0.w;
    a1.x += b1.x; a1.y += b1.y; a1.z += b1.z; a1.w += b1.w;

    float inv = 1.0f / fmaxf((float)(re - rs), 1.0f);
    a0.x *= inv; a0.y *= inv; a0.z *= inv; a0.w *= inv;
    a1.x *= inv; a1.y *= inv; a1.z *= inv; a1.w *= inv;
    float* o = d_hneigh + (size_t)w * 256 + c;
    *(float4*)(o)     = a0;
    *(float4*)(o + 4) = a1;
}

// ---------------- layer-2 aggregation, e1 fused on the fly ----------------
// message = concat(h1[u[e]], relu(P[u[e]] + Q[w] + be));  Q[w] & bias hoisted.
__global__ void agg2_kernel(const float* __restrict__ h1,
                            const float* __restrict__ P,
                            const float* __restrict__ Q,
                            const float* __restrict__ be,
                            const int* __restrict__ u, int n) {
    int w = (blockIdx.x * blockDim.x + threadIdx.x) >> 5;
    int lane = threadIdx.x & 31;
    if (w >= n) return;
    int rs = d_rowstart[w];
    int re = d_rowstart[w + 1];
    int c = lane * 8;
    bool isA = (c < 128);
    int off = isA ? c : (c - 128);

    // hoisted per-node terms for the edge half (Q[w] + bias)
    float4 q0 = make_float4(0.f, 0.f, 0.f, 0.f);
    float4 q1 = make_float4(0.f, 0.f, 0.f, 0.f);
    if (!isA) {
        const float* qp = Q + (size_t)w * 128 + off;
        float4 t0 = *(const float4*)(qp);
        float4 t1 = *(const float4*)(qp + 4);
        float4 c0 = *(const float4*)(be + off);
        float4 c1 = *(const float4*)(be + off + 4);
        q0.x = t0.x + c0.x; q0.y = t0.y + c0.y; q0.z = t0.z + c0.z; q0.w = t0.w + c0.w;
        q1.x = t1.x + c1.x; q1.y = t1.y + c1.y; q1.z = t1.z + c1.z; q1.w = t1.w + c1.w;
    }
    const float* base = isA ? h1 : P;

    float4 a0 = make_float4(0.f, 0.f, 0.f, 0.f);
    float4 a1 = make_float4(0.f, 0.f, 0.f, 0.f);
    for (int p = rs; p < re; ++p) {
        int e = d_edgeidx[p];
        const float* s = base + (size_t)u[e] * 128 + off;
        float4 x0 = *(const float4*)(s);
        float4 x1 = *(const float4*)(s + 4);
        if (!isA) {   // predicated fixup: relu(P[u] + Q[w] + b)
            x0.x = fmaxf(x0.x + q0.x, 0.f); x0.y = fmaxf(x0.y + q0.y, 0.f);
            x0.z = fmaxf(x0.z + q0.z, 0.f); x0.w = fmaxf(x0.w + q0.w, 0.f);
            x1.x = fmaxf(x1.x + q1.x, 0.f); x1.y = fmaxf(x1.y + q1.y, 0.f);
            x1.z = fmaxf(x1.z + q1.z, 0.f); x1.w = fmaxf(x1.w + q1.w, 0.f);
        }
        a0.x += x0.x; a0.y += x0.y; a0.z += x0.z; a0.w += x0.w;
        a1.x += x1.x; a1.y += x1.y; a1.z += x1.z; a1.w += x1.w;
    }
    float inv = 1.0f / fmaxf((float)(re - rs), 1.0f);
    a0.x *= inv; a0.y *= inv; a0.z *= inv; a0.w *= inv;
    a1.x *= inv; a1.y *= inv; a1.z *= inv; a1.w *= inv;
    float* o = d_hneigh + (size_t)w * 256 + c;
    *(float4*)(o)     = a0;
    *(float4*)(o + 4) = a1;
}

// ---------------- final edge combine: e2 = relu(P[u] + Q[v] + b) ----------------
__global__ void edge_combine_kernel(const float* __restrict__ P,
                                    const float* __restrict__ Q,
                                    const float* __restrict__ be,
                                    const int* __restrict__ u,
                                    const int* __restrict__ v,
                                    float* __restrict__ out, int E) {
    int e = (blockIdx.x * blockDim.x + threadIdx.x) >> 5;
    int lane = threadIdx.x & 31;
    if (e >= E) return;
    int uu = u[e], vv = v[e];
    int c = lane * 4;
    float4 p = *(const float4*)(P + (size_t)uu * 128 + c);
    float4 q = *(const float4*)(Q + (size_t)vv * 128 + c);
    float4 b = *(const float4*)(be + c);
    float4 o;
    o.x = fmaxf(p.x + q.x + b.x, 0.f);
    o.y = fmaxf(p.y + q.y + b.y, 0.f);
    o.z = fmaxf(p.z + q.z + b.z, 0.f);
    o.w = fmaxf(p.w + q.w + b.w, 0.f);
    *(float4*)(out + (size_t)e * 128 + c) = o;
}

// ---------------- tf32 mma.sync GEMM ----------------
// C[M,128] = act( X[M,K] @ W'[128,K]^T + bias ), W row o at W + o*Wstride
// X row r = concat(segA[idxA(r)][0:widthA], segB[r][0:widthB])
__device__ __forceinline__ uint32_t f2tf32(float x) {
    uint32_t r;
    asm("cvt.rna.tf32.f32 %0, %1;" : "=r"(r) : "f"(x));
    return r;
}
__device__ __forceinline__ void mma1688(float* c, const uint32_t* a, const uint32_t* b) {
    asm volatile(
        "mma.sync.aligned.m16n8k8.row.col.f32.tf32.tf32.f32 "
        "{%0,%1,%2,%3}, {%4,%5,%6,%7}, {%8,%9}, {%0,%1,%2,%3};"
        : "+f"(c[0]), "+f"(c[1]), "+f"(c[2]), "+f"(c[3])
        : "r"(a[0]), "r"(a[1]), "r"(a[2]), "r"(a[3]), "r"(b[0]), "r"(b[1]));
}

#define RS 20   // smem row stride in words (conflict-free for fragment loads)

__global__ __launch_bounds__(256, 2)
void gemm_tc(const float* __restrict__ segA, const int* __restrict__ idxA, int widthA,
             const float* __restrict__ segB, int widthB,
             const float* __restrict__ W, int Wstride,
             const float* __restrict__ bias, int activate,
             float* __restrict__ C, int M, int K) {
    __shared__ uint32_t Xs[2][128 * RS];
    __shared__ uint32_t Ws[2][128 * RS];

    const int tid  = threadIdx.x;
    const int wid  = tid >> 5;
    const int lane = tid & 31;
    const int blk  = blockIdx.x;
    const int wm   = wid & 1;
    const int wn   = wid >> 1;
    const int g    = lane >> 2;
    const int t    = lane & 3;

    const int rloc = tid >> 1;
    const int kh   = (tid & 1) * 8;
    int grow = blk * 128 + rloc;
    int grd  = (grow < M) ? grow : 0;
    const float* pA = segA + (size_t)(idxA ? idxA[grd] : grd) * widthA;
    const float* pB = segB + (size_t)grd * widthB;
    const float* pW = W + (size_t)rloc * Wstride;

    float cacc[4][4][4];
    #pragma unroll
    for (int mi = 0; mi < 4; ++mi)
        #pragma unroll
        for (int ni = 0; ni < 4; ++ni)
            #pragma unroll
            for (int r = 0; r < 4; ++r) cacc[mi][ni][r] = 0.f;

    const int NC = K >> 4;
    float4 px0, px1, pw0, pw1;

    {
        int k = kh;
        px0 = (k < widthA) ? *(const float4*)(pA + k) : *(const float4*)(pB + (k - widthA));
        k += 4;
        px1 = (k < widthA) ? *(const float4*)(pA + k) : *(const float4*)(pB + (k - widthA));
        pw0 = *(const float4*)(pW + kh);
        pw1 = *(const float4*)(pW + kh + 4);
        uint32_t* dx = &Xs[0][rloc * RS + kh];
        uint32_t* dw = &Ws[0][rloc * RS + kh];
        dx[0] = f2tf32(px0.x); dx[1] = f2tf32(px0.y); dx[2] = f2tf32(px0.z); dx[3] = f2tf32(px0.w);
        dx[4] = f2tf32(px1.x); dx[5] = f2tf32(px1.y); dx[6] = f2tf32(px1.z); dx[7] = f2tf32(px1.w);
        dw[0] = f2tf32(pw0.x); dw[1] = f2tf32(pw0.y); dw[2] = f2tf32(pw0.z); dw[3] = f2tf32(pw0.w);
        dw[4] = f2tf32(pw1.x); dw[5] = f2tf32(pw1.y); dw[6] = f2tf32(pw1.z); dw[7] = f2tf32(pw1.w);
    }
    __syncthreads();

    for (int c = 0; c < NC; ++c) {
        if (c + 1 < NC) {
            int kb = (c + 1) * 16 + kh;
            int k = kb;
            px0 = (k < widthA) ? *(const float4*)(pA + k) : *(const float4*)(pB + (k - widthA));
            k += 4;
            px1 = (k < widthA) ? *(const float4*)(pA + k) : *(const float4*)(pB + (k - widthA));
            pw0 = *(const float4*)(pW + kb);
            pw1 = *(const float4*)(pW + kb + 4);
        }

        const int buf = c & 1;
        #pragma unroll
        for (int ks = 0; ks < 2; ++ks) {
            const int ko = ks * 8;
            uint32_t af[4][4];
            #pragma unroll
            for (int mi = 0; mi < 4; ++mi) {
                int r0 = (wm * 64 + mi * 16 + g) * RS + ko + t;
                af[mi][0] = Xs[buf][r0];
                af[mi][1] = Xs[buf][r0 + 8 * RS];
                af[mi][2] = Xs[buf][r0 + 4];
                af[mi][3] = Xs[buf][r0 + 8 * RS + 4];
            }
            #pragma unroll
            for (int ni = 0; ni < 4; ++ni) {
                uint32_t bf[2];
                int n0 = (wn * 32 + ni * 8 + g) * RS + ko + t;
                bf[0] = Ws[buf][n0];
                bf[1] = Ws[buf][n0 + 4];
                #pragma unroll
                for (int mi = 0; mi < 4; ++mi)
                    mma1688(cacc[mi][ni], af[mi], bf);
            }
        }

        if (c + 1 < NC) {
            const int nb = (c + 1) & 1;
            uint32_t* dx = &Xs[nb][rloc * RS + kh];
            uint32_t* dw = &Ws[nb][rloc * RS + kh];
            dx[0] = f2tf32(px0.x); dx[1] = f2tf32(px0.y); dx[2] = f2tf32(px0.z); dx[3] = f2tf32(px0.w);
            dx[4] = f2tf32(px1.x); dx[5] = f2tf32(px1.y); dx[6] = f2tf32(px1.z); dx[7] = f2tf32(px1.w);
            dw[0] = f2tf32(pw0.x); dw[1] = f2tf32(pw0.y); dw[2] = f2tf32(pw0.z); dw[3] = f2tf32(pw0.w);
            dw[4] = f2tf32(pw1.x); dw[5] = f2tf32(pw1.y); dw[6] = f2tf32(pw1.z); dw[7] = f2tf32(pw1.w);
            __syncthreads();
        }
    }

    #pragma unroll
    for (int ni = 0; ni < 4; ++ni) {
        int col = wn * 32 + ni * 8 + t * 2;
        float b0 = bias ? bias[col] : 0.f;
        float b1 = bias ? bias[col + 1] : 0.f;
        #pragma unroll
        for (int mi = 0; mi < 4; ++mi) {
            int rb = blk * 128 + wm * 64 + mi * 16 + g;
            if (rb < M) {
                float2 o;
                o.x = cacc[mi][ni][0] + b0;
                o.y = cacc[mi][ni][1] + b1;
                if (activate) { o.x = fmaxf(o.x, 0.f); o.y = fmaxf(o.y, 0.f); }
                *(float2*)(C + (size_t)rb * 128 + col) = o;
            }
            if (rb + 8 < M) {
                float2 o;
                o.x = cacc[mi][ni][2] + b0;
                o.y = cacc[mi][ni][3] + b1;
                if (activate) { o.x = fmaxf(o.x, 0.f); o.y = fmaxf(o.y, 0.f); }
                *(float2*)(C + (size_t)(rb + 8) * 128 + col) = o;
            }
        }
    }
}

// ---------------- launch ----------------
extern "C" void kernel_launch(void* const* d_in, const int* in_sizes, int n_in,
                              void* d_out, int out_size) {
    const float* nf  = (const float*)d_in[0];
    const float* ef  = (const float*)d_in[1];
    const int*   u   = (const int*)d_in[2];
    const int*   v   = (const int*)d_in[3];
    const float* W1a = (const float*)d_in[4];
    const float* b1a = (const float*)d_in[5];
    const float* W1e = (const float*)d_in[6];
    const float* b1e = (const float*)d_in[7];
    const float* W2a = (const float*)d_in[8];
    const float* b2a = (const float*)d_in[9];
    const float* W2e = (const float*)d_in[10];
    const float* b2e = (const float*)d_in[11];
    float* out = (float*)d_out;

    int N = in_sizes[0] / 128;
    int E = in_sizes[2];
    if (N > NN) N = NN;
    if (E > EE) E = EE;

    float *hneigh, *h1, *P, *Q;
    cudaGetSymbolAddress((void**)&hneigh, d_hneigh);
    cudaGetSymbolAddress((void**)&h1, d_h1);
    cudaGetSymbolAddress((void**)&P, d_P);
    cudaGetSymbolAddress((void**)&Q, d_Q);

    // CSR by destination
    zero_counts_kernel<<<(N + 255) / 256, 256>>>(N);
    hist_kernel<<<(E + 255) / 256, 256>>>(v, E);
    scan_kernel<<<1, 1024>>>(N);
    bucket_kernel<<<(E + 255) / 256, 256>>>(v, E);

    int nb_node = (N + 127) / 128;

    // ---- layer 1 ----
    agg_kernel<<<(N + 7) / 8, 256>>>(nf, ef, u, N);
    gemm_tc<<<nb_node, 256>>>(nf, nullptr, 128, hneigh, 256,
                              W1a, 384, b1a, 1, h1, N, 384);
    // P1 = h1 @ We_L^T, Q1 = h1 @ We_R^T (no bias/relu; fused later)
    gemm_tc<<<nb_node, 256>>>(h1, nullptr, 128, h1, 0,
                              W1e, 256, nullptr, 0, P, N, 128);
    gemm_tc<<<nb_node, 256>>>(h1, nullptr, 128, h1, 0,
                              W1e + 128, 256, nullptr, 0, Q, N, 128);

    // ---- layer 2 ----
    agg2_kernel<<<(N + 7) / 8, 256>>>(h1, P, Q, b1e, u, N);
    gemm_tc<<<nb_node, 256>>>(h1, nullptr, 128, hneigh, 256,
                              W2a, 384, b2a, 1, out, N, 384);
    gemm_tc<<<nb_node, 256>>>(out, nullptr, 128, out, 0,
                              W2e, 256, nullptr, 0, P, N, 128);
    gemm_tc<<<nb_node, 256>>>(out, nullptr, 128, out, 0,
                              W2e + 128, 256, nullptr, 0, Q, N, 128);
    edge_combine_kernel<<<(E + 7) / 8, 256>>>(P, Q, b2e, u, v,
                                              out + (size_t)N * 128, E);
}